// round 16
// baseline (speedup 1.0000x reference)
#include <cuda_runtime.h>
#include <math.h>

typedef unsigned long long u64;

// ---- packed f32x2 helpers --------------------------------------------------
__device__ __forceinline__ u64 fma2(u64 a, u64 b, u64 c) {
    u64 d; asm("fma.rn.f32x2 %0, %1, %2, %3;" : "=l"(d) : "l"(a), "l"(b), "l"(c)); return d;
}
__device__ __forceinline__ u64 mul2(u64 a, u64 b) {
    u64 d; asm("mul.rn.f32x2 %0, %1, %2;" : "=l"(d) : "l"(a), "l"(b)); return d;
}
__device__ __forceinline__ float rcp_approx(float x) {
    float r; asm("rcp.approx.f32 %0, %1;" : "=f"(r) : "f"(x)); return r;
}
__device__ __forceinline__ float ex2_approx(float x) {
    float r; asm("ex2.approx.f32 %0, %1;" : "=f"(r) : "f"(x)); return r;
}

// Fast exact-GELU: Abramowitz-Stegun 7.1.26 erf (|abs err| <= 1.5e-7).
__device__ __forceinline__ float gelu_fast(float t) {
    float z  = fabsf(t) * 0.70710678118654752f;
    float k  = rcp_approx(fmaf(0.3275911f, z, 1.0f));
    float w  = fmaf(fmaf(fmaf(fmaf(1.061405429f, k, -1.453152027f), k,
                               1.421413741f), k, -0.284496736f), k,
                    0.254829592f) * k;
    float e  = ex2_approx(-1.4426950408889634f * z * z);
    float erfz = fmaf(-w, e, 1.0f);               // erf(z), z >= 0
    float cdf  = fmaf(0.5f, copysignf(erfz, t), 0.5f);
    return t * cdf;
}

// ---------------------------------------------------------------------------
// Constant-bank weight layout (floats).
// ---------------------------------------------------------------------------
#define OFF_LNW  0      // [4][5]
#define OFF_LNB  20     // [4][5]
#define OFF_BW   40     // [4][5][9]
#define OFF_BB   220    // [4][5]
#define OFF_BS   240    // [4][5]
#define OFF_WW   260    // [4][5][4][9]
#define OFF_WS   980    // [4][5][4]
#define OFF_PW   1060   // [4][5][5]
#define OFF_TLW  1160   // [20]
#define OFF_TLB  1180   // [20]
#define OFF_TW   1200   // [8][20]
#define OFF_TB   1360   // [8]
#define OFF_RW   1368   // [8][9]
#define OFF_RB   1440   // [8]
#define OFF_PREW 1448   // [8][16]
#define OFF_PREB 1576   // [8]
#define W_TOTAL  1584

__constant__ float cW[W_TOTAL];
__device__ float g_wpack[W_TOTAL];

// Scratch: xh projected to 8 channels at 256x256.  [8][8][256][256]
__device__ float g_xhp[8 * 8 * 256 * 256];

// ---------------------------------------------------------------------------
// pack_kernel: gather all weight arrays into g_wpack (one memcpy -> cW).
// ---------------------------------------------------------------------------
__global__ __launch_bounds__(256) void pack_kernel(
    const float* __restrict__ lnw, const float* __restrict__ lnb,
    const float* __restrict__ bw,  const float* __restrict__ bb,
    const float* __restrict__ bs,  const float* __restrict__ ww,
    const float* __restrict__ ws,  const float* __restrict__ pw,
    const float* __restrict__ tlw, const float* __restrict__ tlb,
    const float* __restrict__ tw,  const float* __restrict__ tb,
    const float* __restrict__ rw,  const float* __restrict__ rb,
    const float* __restrict__ prew, const float* __restrict__ preb)
{
    int i = blockIdx.x * 256 + threadIdx.x;
    if (i >= W_TOTAL) return;
    float v;
    if      (i < OFF_LNB)  v = lnw[i - OFF_LNW];
    else if (i < OFF_BW)   v = lnb[i - OFF_LNB];
    else if (i < OFF_BB)   v = bw[i - OFF_BW];
    else if (i < OFF_BS)   v = bb[i - OFF_BB];
    else if (i < OFF_WW)   v = bs[i - OFF_BS];
    else if (i < OFF_WS)   v = ww[i - OFF_WW];
    else if (i < OFF_PW)   v = ws[i - OFF_WS];
    else if (i < OFF_TLW)  v = pw[i - OFF_PW];
    else if (i < OFF_TLB)  v = tlw[i - OFF_TLW];
    else if (i < OFF_TW)   v = tlb[i - OFF_TLB];
    else if (i < OFF_TB)   v = tw[i - OFF_TW];
    else if (i < OFF_RW)   v = tb[i - OFF_TB];
    else if (i < OFF_RB)   v = rw[i - OFF_RW];
    else if (i < OFF_PREW) v = rb[i - OFF_RB];
    else if (i < OFF_PREB) v = prew[i - OFF_PREW];
    else                   v = preb[i - OFF_PREB];
    g_wpack[i] = v;
}

// ---------------------------------------------------------------------------
// Kernel 1: pre_project  xh[8,16,256,256] -> g_xhp
// ---------------------------------------------------------------------------
__global__ __launch_bounds__(256) void pre_kernel(const float* __restrict__ xh)
{
    int idx = blockIdx.x * 256 + threadIdx.x;   // covers 8*65536 exactly
    int b   = idx >> 16;
    int pix = idx & 65535;
    const float* px = xh + (size_t)b * 16 * 65536 + pix;
    float in[16];
#pragma unroll
    for (int c = 0; c < 16; c++) in[c] = __ldg(px + (size_t)c * 65536);
#pragma unroll
    for (int o = 0; o < 8; o++) {
        float s = cW[OFF_PREB + o];
#pragma unroll
        for (int c = 0; c < 16; c++) s += cW[OFF_PREW + o * 16 + c] * in[c];
        g_xhp[((size_t)b * 8 + o) * 65536 + pix] = s;
    }
}

// ---------------------------------------------------------------------------
// Per-branch body for a 64x16 tile, 512 threads.
// Template BR folds weight indices into FFMA operands. Phase 1 scalar;
// phases 2/3 packed loads/FFMA2; phase 4 vertical pixel pair per thread.
// ---------------------------------------------------------------------------
template<int BR>
__device__ __forceinline__ void do_branch(
    int tid, int x0, int y0, int b,
    const float* __restrict__ xl, const float* __restrict__ mask,
    float (&S)[5][20][68], float4 (&CX4)[5][10][34], float4 (&TAG4)[5][8][32],
    const float2* __restrict__ sWW2, const float2* __restrict__ sWS2,
    float* pA, float* pB, float& s1A, float& s2A, float& s1B, float& s2B)
{
    __syncthreads();   // protect S/CX/TAG reuse across branches

    // ---- phase 1: load + bilinear upsample + channel-LN into S (scalar) -
    for (int hp = tid; hp < 1360; hp += 512) {
        int sr = hp / 68;
        int sc = hp - sr * 68;
        int y = y0 - 2 + sr, x = x0 - 2 + sc;
        float v0 = 0.f, v1 = 0.f, v2 = 0.f, v3 = 0.f, v4 = 0.f;
        if ((unsigned)y < 512u && (unsigned)x < 512u) {
            const float SC = (float)(255.0 / 511.0);
            float cy = (float)y * SC;
            int   iy = (int)cy; iy = iy > 254 ? 254 : iy;
            float fy = cy - (float)iy;
            float cxx = (float)x * SC;
            int   ix = (int)cxx; ix = ix > 254 ? 254 : ix;
            float fx = cxx - (float)ix;
            float w00 = (1.f - fy) * (1.f - fx);
            float w01 = (1.f - fy) * fx;
            float w10 = fy * (1.f - fx);
            float w11 = fy * fx;
            const float* p0 = g_xhp + (((size_t)b * 8 + 2 * BR) * 256 + iy) * 256 + ix;
            const float* p1 = p0 + 65536;
            v0 = w00 * p0[0] + w01 * p0[1] + w10 * p0[256] + w11 * p0[257];
            v1 = w00 * p1[0] + w01 * p1[1] + w10 * p1[256] + w11 * p1[257];
            size_t xi = (((size_t)b * 8 + 2 * BR) * 512 + y) * 512 + x;
            v2 = __ldg(xl + xi);
            v3 = __ldg(xl + xi + 262144);
            v4 = __ldg(mask + ((size_t)b * 512 + y) * 512 + x);
            float u = 0.2f * (v0 + v1 + v2 + v3 + v4);
            float d0 = v0 - u, d1 = v1 - u, d2 = v2 - u, d3 = v3 - u, d4 = v4 - u;
            float var = 0.2f * (d0 * d0 + d1 * d1 + d2 * d2 + d3 * d3 + d4 * d4);
            float inv = rsqrtf(var + 1e-6f);
            v0 = cW[OFF_LNW + BR * 5 + 0] * (d0 * inv) + cW[OFF_LNB + BR * 5 + 0];
            v1 = cW[OFF_LNW + BR * 5 + 1] * (d1 * inv) + cW[OFF_LNB + BR * 5 + 1];
            v2 = cW[OFF_LNW + BR * 5 + 2] * (d2 * inv) + cW[OFF_LNB + BR * 5 + 2];
            v3 = cW[OFF_LNW + BR * 5 + 3] * (d3 * inv) + cW[OFF_LNB + BR * 5 + 3];
            v4 = cW[OFF_LNW + BR * 5 + 4] * (d4 * inv) + cW[OFF_LNB + BR * 5 + 4];
        }
        S[0][sr][sc] = v0; S[1][sr][sc] = v1; S[2][sr][sc] = v2;
        S[3][sr][sc] = v3; S[4][sr][sc] = v4;
    }
    __syncthreads();

    // ---- phase 2: Haar butterflies, 2 cells/item via LDS.128 ------------
    for (int t = tid; t < 850; t += 512) {
        int c = t / 170; int cell = t - c * 170;
        int ci = cell / 17; int cjp = cell - ci * 17;  // col pair 2cjp, 2cjp+1
        int sr = 2 * ci, sc = 4 * cjp;
        float4 r0 = *(const float4*)&S[c][sr][sc];
        float4 r1 = *(const float4*)&S[c][sr + 1][sc];
        float su1 = r0.x + r0.y, dd1 = r0.x - r0.y;
        float su2 = r1.x + r1.y, dd2 = r1.x - r1.y;
        CX4[c][ci][2 * cjp] = make_float4(0.5f * (su1 + su2), 0.5f * (su1 - su2),
                                          0.5f * (dd1 + dd2), 0.5f * (dd1 - dd2));
        float su3 = r0.z + r0.w, dd3 = r0.z - r0.w;
        float su4 = r1.z + r1.w, dd4 = r1.z - r1.w;
        CX4[c][ci][2 * cjp + 1] = make_float4(0.5f * (su3 + su4), 0.5f * (su3 - su4),
                                              0.5f * (dd3 + dd4), 0.5f * (dd3 - dd4));
    }
    __syncthreads();

    // ---- phase 3: 3x3 conv on packed subband pairs (FFMA2) -> TAG4 ------
    for (int t = tid; t < 640; t += 512) {
        int kp = t & 1;             // subband pair (2kp, 2kp+1)
        int qj = ((t >> 1) & 7) * 4;
        int ti = (t >> 4) & 7;      // 0..7
        int c  = t >> 7;            // 0..4
        const u64* wv2 = ((const u64*)sWW2) + ((BR * 5 + c) * 2 + kp) * 9;
        u64 a0 = 0, a1 = 0, a2 = 0, a3 = 0;
#pragma unroll
        for (int dy = 0; dy < 3; dy++) {
            u64 row[6];
#pragma unroll
            for (int dx = 0; dx < 6; dx++)
                row[dx] = ((const u64*)&CX4[c][ti + dy][qj + dx])[kp];
#pragma unroll
            for (int dx = 0; dx < 3; dx++) {
                u64 w2 = wv2[dy * 3 + dx];
                a0 = fma2(w2, row[dx],     a0);
                a1 = fma2(w2, row[dx + 1], a1);
                a2 = fma2(w2, row[dx + 2], a2);
                a3 = fma2(w2, row[dx + 3], a3);
            }
        }
        u64 ws2 = ((const u64*)sWS2)[(BR * 5 + c) * 2 + kp];
        ((u64*)&TAG4[c][ti][qj + 0])[kp] = mul2(a0, ws2);
        ((u64*)&TAG4[c][ti][qj + 1])[kp] = mul2(a1, ws2);
        ((u64*)&TAG4[c][ti][qj + 2])[kp] = mul2(a2, ws2);
        ((u64*)&TAG4[c][ti][qj + 3])[kp] = mul2(a3, ws2);
    }
    __syncthreads();

    // ---- phase 4: base conv + iDWT + pointwise for vertical pixel pair --
    {
        int tx = tid & 63, tyh = tid >> 6;   // pixels rows 2tyh, 2tyh+1
        int ci = tyh, cj = tx >> 1;
        int px = tx & 1;
        float o5A[5] = {0.f, 0.f, 0.f, 0.f, 0.f};
        float o5B[5] = {0.f, 0.f, 0.f, 0.f, 0.f};
#pragma unroll
        for (int c = 0; c < 5; c++) {
            float w4[4][3];
#pragma unroll
            for (int dy = 0; dy < 4; dy++)
#pragma unroll
                for (int dx = 0; dx < 3; dx++)
                    w4[dy][dx] = S[c][2 * tyh + 1 + dy][tx + 1 + dx];
            float sA = 0.f, sB = 0.f;
#pragma unroll
            for (int dy = 0; dy < 3; dy++)
#pragma unroll
                for (int dx = 0; dx < 3; dx++) {
                    float wgt = cW[OFF_BW + (BR * 5 + c) * 9 + dy * 3 + dx];
                    sA += wgt * w4[dy][dx];
                    sB += wgt * w4[dy + 1][dx];
                }
            sA = (sA + cW[OFF_BB + BR * 5 + c]) * cW[OFF_BS + BR * 5 + c];
            sB = (sB + cW[OFF_BB + BR * 5 + c]) * cW[OFF_BS + BR * 5 + c];
            float4 tg = TAG4[c][ci][cj];           // shared by both pixels
            float t2 = px ? -tg.z : tg.z;
            float t3A = px ? -tg.w : tg.w;
            float vA = sA + 0.5f * (tg.x + tg.y + t2 + t3A);
            float t3B = px ? tg.w : -tg.w;
            float vB = sB + 0.5f * (tg.x - tg.y + t2 + t3B);
#pragma unroll
            for (int o = 0; o < 5; o++) {
                float pwv = cW[OFF_PW + BR * 25 + o * 5 + c];
                o5A[o] += pwv * vA;
                o5B[o] += pwv * vB;
            }
        }
#pragma unroll
        for (int jj = 0; jj < 5; jj++) {
            float vA = o5A[jj], vB = o5B[jj];
            s1A += vA; s2A += vA * vA;
            s1B += vB; s2B += vB * vB;
            float vsA = cW[OFF_TLW + BR * 5 + jj] * vA;
            float vsB = cW[OFF_TLW + BR * 5 + jj] * vB;
#pragma unroll
            for (int o = 0; o < 8; o++) {
                float tw = cW[OFF_TW + o * 20 + BR * 5 + jj];
                pA[o] += tw * vsA;
                pB[o] += tw * vsB;
            }
        }
    }
}

// ---------------------------------------------------------------------------
// Kernel 2: fused branches + tail + residual.
// 64x16 tile, 512 threads, vertical pixel pair per thread, 2 blocks/SM.
// ---------------------------------------------------------------------------
__global__ __launch_bounds__(512, 2) void fused_kernel(
    const float* __restrict__ xl,        // [8,8,512,512]
    const float* __restrict__ mask,      // [8,1,512,512]
    const float* __restrict__ g_wt_w,    // [4,20,3,3]
    const float* __restrict__ g_wt_s,    // [4,20]
    float* __restrict__ out)             // [8,8,512,512]
{
    __shared__ float2 sWW2[360];         // packed (k, k+1) wavelet weights
    __shared__ float2 sWS2[40];
    __shared__ float sRS[8];             // row sums of folded tail matrix
    __shared__ float sC[8];              // folded LN-bias + tail bias
    __shared__ __align__(16) float  S[5][20][68];
    __shared__ float4 CX4[5][10][34];
    __shared__ float4 TAG4[5][8][32];

    const int tid = threadIdx.x;
    for (int t = tid; t < 360; t += 512) {
        int pairIdx = t / 9, tap = t - (t / 9) * 9;
        int chbase = (pairIdx >> 1) * 4 + (pairIdx & 1) * 2;
        sWW2[t] = make_float2(g_wt_w[chbase * 9 + tap], g_wt_w[(chbase + 1) * 9 + tap]);
    }
    for (int t = tid; t < 40; t += 512) {
        int base = (t >> 1) * 4 + (t & 1) * 2;
        sWS2[t] = make_float2(g_wt_s[base], g_wt_s[base + 1]);
    }
    if (tid < 8) {
        float rs = 0.f, C = cW[OFF_TB + tid];
#pragma unroll
        for (int j = 0; j < 20; j++) {
            float w = cW[OFF_TW + tid * 20 + j];
            rs += w * cW[OFF_TLW + j];
            C  += w * cW[OFF_TLB + j];
        }
        sRS[tid] = rs;
        sC[tid]  = C;
    }

    const int x0 = blockIdx.x * 64;
    const int y0 = blockIdx.y * 16;
    const int b  = blockIdx.z;

    float pA[8] = {0.f, 0.f, 0.f, 0.f, 0.f, 0.f, 0.f, 0.f};
    float pB[8] = {0.f, 0.f, 0.f, 0.f, 0.f, 0.f, 0.f, 0.f};
    float s1A = 0.f, s2A = 0.f, s1B = 0.f, s2B = 0.f;

    do_branch<0>(tid, x0, y0, b, xl, mask, S, CX4, TAG4, sWW2, sWS2, pA, pB, s1A, s2A, s1B, s2B);
    do_branch<1>(tid, x0, y0, b, xl, mask, S, CX4, TAG4, sWW2, sWS2, pA, pB, s1A, s2A, s1B, s2B);
    do_branch<2>(tid, x0, y0, b, xl, mask, S, CX4, TAG4, sWW2, sWS2, pA, pB, s1A, s2A, s1B, s2B);
    do_branch<3>(tid, x0, y0, b, xl, mask, S, CX4, TAG4, sWW2, sWS2, pA, pB, s1A, s2A, s1B, s2B);

    // ---- tail: folded LN(20)+matmul -> fast exact GELU, + residual ------
    const int tx = tid & 63, tyh = tid >> 6;
#pragma unroll
    for (int pp = 0; pp < 2; pp++) {
        float* p  = pp ? pB : pA;
        float s1  = pp ? s1B : s1A;
        float s2  = pp ? s2B : s2A;
        float u   = s1 * 0.05f;
        float var = fmaxf(s2 * 0.05f - u * u, 0.f);
        float inv = rsqrtf(var + 1e-6f);

        int y = y0 + 2 * tyh + pp, x = x0 + tx;
        size_t pix = (size_t)y * 512 + x;
        float xv[8];
#pragma unroll
        for (int c = 0; c < 8; c++)
            xv[c] = __ldg(xl + ((size_t)b * 8 + c) * 262144 + pix);
        float mv = __ldg(mask + (size_t)b * 262144 + pix);

#pragma unroll
        for (int o = 0; o < 8; o++) {
            float t = inv * (p[o] - u * sRS[o]) + sC[o];
            float gel = gelu_fast(t);
            float r = cW[OFF_RB + o];
#pragma unroll
            for (int c = 0; c < 8; c++) r += cW[OFF_RW + o * 9 + c] * xv[c];
            r += cW[OFF_RW + o * 9 + 8] * mv;
            out[((size_t)b * 8 + o) * 262144 + pix] = gel + r;
        }
    }
}

// ---------------------------------------------------------------------------
// kernel_launch
// Inputs: 0 xh, 1 xl, 2 mask, 3 pre_w, 4 pre_b, 5 g_ln_w, 6 g_ln_b,
//  7 g_base_w, 8 g_base_b, 9 g_base_s, 10 g_wt_w, 11 g_wt_s, 12 g_pw_w,
// 13 tail_ln_w, 14 tail_ln_b, 15 tail_w, 16 tail_b, 17 res_w, 18 res_b
// ---------------------------------------------------------------------------
extern "C" void kernel_launch(void* const* d_in, const int* in_sizes, int n_in,
                              void* d_out, int out_size)
{
    (void)in_sizes; (void)n_in; (void)out_size;
    const float* xh   = (const float*)d_in[0];
    const float* xl   = (const float*)d_in[1];
    const float* mask = (const float*)d_in[2];
    float* out = (float*)d_out;

    pack_kernel<<<(W_TOTAL + 255) / 256, 256>>>(
        (const float*)d_in[5],  (const float*)d_in[6],
        (const float*)d_in[7],  (const float*)d_in[8],
        (const float*)d_in[9],  (const float*)d_in[10],
        (const float*)d_in[11], (const float*)d_in[12],
        (const float*)d_in[13], (const float*)d_in[14],
        (const float*)d_in[15], (const float*)d_in[16],
        (const float*)d_in[17], (const float*)d_in[18],
        (const float*)d_in[3],  (const float*)d_in[4]);

    void* wpack_ptr = nullptr;
    cudaGetSymbolAddress(&wpack_ptr, g_wpack);
    cudaMemcpyToSymbolAsync(cW, wpack_ptr, W_TOTAL * sizeof(float), 0,
                            cudaMemcpyDeviceToDevice, 0);

    pre_kernel<<<2048, 256>>>(xh);

    dim3 grid(512 / 64, 512 / 16, 8);   // 8 x 32 x 8 tiles
    fused_kernel<<<grid, 512>>>(xl, mask,
                                (const float*)d_in[10], (const float*)d_in[11],
                                out);
}

// round 17
// speedup vs baseline: 1.3008x; 1.3008x over previous
#include <cuda_runtime.h>
#include <math.h>

typedef unsigned long long u64;

// ---- packed f32x2 helpers --------------------------------------------------
__device__ __forceinline__ u64 fma2(u64 a, u64 b, u64 c) {
    u64 d; asm("fma.rn.f32x2 %0, %1, %2, %3;" : "=l"(d) : "l"(a), "l"(b), "l"(c)); return d;
}
__device__ __forceinline__ u64 mul2(u64 a, u64 b) {
    u64 d; asm("mul.rn.f32x2 %0, %1, %2;" : "=l"(d) : "l"(a), "l"(b)); return d;
}
__device__ __forceinline__ float rcp_approx(float x) {
    float r; asm("rcp.approx.f32 %0, %1;" : "=f"(r) : "f"(x)); return r;
}
__device__ __forceinline__ float ex2_approx(float x) {
    float r; asm("ex2.approx.f32 %0, %1;" : "=f"(r) : "f"(x)); return r;
}

// Fast exact-GELU: Abramowitz-Stegun 7.1.26 erf (|abs err| <= 1.5e-7).
__device__ __forceinline__ float gelu_fast(float t) {
    float z  = fabsf(t) * 0.70710678118654752f;
    float k  = rcp_approx(fmaf(0.3275911f, z, 1.0f));
    float w  = fmaf(fmaf(fmaf(fmaf(1.061405429f, k, -1.453152027f), k,
                               1.421413741f), k, -0.284496736f), k,
                    0.254829592f) * k;
    float e  = ex2_approx(-1.4426950408889634f * z * z);
    float erfz = fmaf(-w, e, 1.0f);               // erf(z), z >= 0
    float cdf  = fmaf(0.5f, copysignf(erfz, t), 0.5f);
    return t * cdf;
}

// ---------------------------------------------------------------------------
// Constant-bank weight layout (floats).
// ---------------------------------------------------------------------------
#define OFF_LNW  0      // [4][5]
#define OFF_LNB  20     // [4][5]
#define OFF_BW   40     // [4][5][9]
#define OFF_BB   220    // [4][5]
#define OFF_BS   240    // [4][5]
#define OFF_WW   260    // [4][5][4][9]
#define OFF_WS   980    // [4][5][4]
#define OFF_PW   1060   // [4][5][5]
#define OFF_TLW  1160   // [20]
#define OFF_TLB  1180   // [20]
#define OFF_TW   1200   // [8][20]
#define OFF_TB   1360   // [8]
#define OFF_RW   1368   // [8][9]
#define OFF_RB   1440   // [8]
#define OFF_PREW 1448   // [8][16]
#define OFF_PREB 1576   // [8]
#define W_TOTAL  1584

__constant__ float cW[W_TOTAL];
__device__ float g_wpack[W_TOTAL];

// Scratch: xh projected to 8 channels at 256x256.  [8][8][256][256]
__device__ float g_xhp[8 * 8 * 256 * 256];

// ---------------------------------------------------------------------------
// pack_kernel: gather all weight arrays into g_wpack (one memcpy -> cW).
// ---------------------------------------------------------------------------
__global__ __launch_bounds__(256) void pack_kernel(
    const float* __restrict__ lnw, const float* __restrict__ lnb,
    const float* __restrict__ bw,  const float* __restrict__ bb,
    const float* __restrict__ bs,  const float* __restrict__ ww,
    const float* __restrict__ ws,  const float* __restrict__ pw,
    const float* __restrict__ tlw, const float* __restrict__ tlb,
    const float* __restrict__ tw,  const float* __restrict__ tb,
    const float* __restrict__ rw,  const float* __restrict__ rb,
    const float* __restrict__ prew, const float* __restrict__ preb)
{
    int i = blockIdx.x * 256 + threadIdx.x;
    if (i >= W_TOTAL) return;
    float v;
    if      (i < OFF_LNB)  v = lnw[i - OFF_LNW];
    else if (i < OFF_BW)   v = lnb[i - OFF_LNB];
    else if (i < OFF_BB)   v = bw[i - OFF_BW];
    else if (i < OFF_BS)   v = bb[i - OFF_BB];
    else if (i < OFF_WW)   v = bs[i - OFF_BS];
    else if (i < OFF_WS)   v = ww[i - OFF_WW];
    else if (i < OFF_PW)   v = ws[i - OFF_WS];
    else if (i < OFF_TLW)  v = pw[i - OFF_PW];
    else if (i < OFF_TLB)  v = tlw[i - OFF_TLW];
    else if (i < OFF_TW)   v = tlb[i - OFF_TLB];
    else if (i < OFF_TB)   v = tw[i - OFF_TW];
    else if (i < OFF_RW)   v = tb[i - OFF_TB];
    else if (i < OFF_RB)   v = rw[i - OFF_RW];
    else if (i < OFF_PREW) v = rb[i - OFF_RB];
    else if (i < OFF_PREB) v = prew[i - OFF_PREW];
    else                   v = preb[i - OFF_PREB];
    g_wpack[i] = v;
}

// ---------------------------------------------------------------------------
// Kernel 1: pre_project  xh[8,16,256,256] -> g_xhp
// ---------------------------------------------------------------------------
__global__ __launch_bounds__(256) void pre_kernel(const float* __restrict__ xh)
{
    int idx = blockIdx.x * 256 + threadIdx.x;   // covers 8*65536 exactly
    int b   = idx >> 16;
    int pix = idx & 65535;
    const float* px = xh + (size_t)b * 16 * 65536 + pix;
    float in[16];
#pragma unroll
    for (int c = 0; c < 16; c++) in[c] = __ldg(px + (size_t)c * 65536);
#pragma unroll
    for (int o = 0; o < 8; o++) {
        float s = cW[OFF_PREB + o];
#pragma unroll
        for (int c = 0; c < 16; c++) s += cW[OFF_PREW + o * 16 + c] * in[c];
        g_xhp[((size_t)b * 8 + o) * 65536 + pix] = s;
    }
}

// ---------------------------------------------------------------------------
// Phase-1 item: branch-free (clamped addresses + select at store).
// ---------------------------------------------------------------------------
template<int BR>
__device__ __forceinline__ void p1_item(
    int hp, int x0, int y0, int b,
    const float* __restrict__ xl, const float* __restrict__ mask,
    float (&S)[5][20][36])
{
    int sr = hp / 36;
    int sc = hp - sr * 36;
    int y = y0 - 2 + sr, x = x0 - 2 + sc;
    bool in = ((unsigned)y < 512u) && ((unsigned)x < 512u);
    int yc = min(max(y, 0), 511);
    int xc = min(max(x, 0), 511);
    const float SC = (float)(255.0 / 511.0);
    float cy = (float)yc * SC;
    int   iy = (int)cy; iy = iy > 254 ? 254 : iy;
    float fy = cy - (float)iy;
    float cxx = (float)xc * SC;
    int   ix = (int)cxx; ix = ix > 254 ? 254 : ix;
    float fx = cxx - (float)ix;
    float w00 = (1.f - fy) * (1.f - fx);
    float w01 = (1.f - fy) * fx;
    float w10 = fy * (1.f - fx);
    float w11 = fy * fx;
    const float* p0 = g_xhp + (((size_t)b * 8 + 2 * BR) * 256 + iy) * 256 + ix;
    const float* p1 = p0 + 65536;
    float v0 = w00 * p0[0] + w01 * p0[1] + w10 * p0[256] + w11 * p0[257];
    float v1 = w00 * p1[0] + w01 * p1[1] + w10 * p1[256] + w11 * p1[257];
    size_t pix = (size_t)yc * 512 + xc;
    size_t xi = ((size_t)b * 8 + 2 * BR) * 262144 + pix;
    float v2 = __ldg(xl + xi);
    float v3 = __ldg(xl + xi + 262144);
    float v4 = __ldg(mask + (size_t)b * 262144 + pix);
    float u = 0.2f * (v0 + v1 + v2 + v3 + v4);
    float d0 = v0 - u, d1 = v1 - u, d2 = v2 - u, d3 = v3 - u, d4 = v4 - u;
    float var = 0.2f * (d0 * d0 + d1 * d1 + d2 * d2 + d3 * d3 + d4 * d4);
    float inv = rsqrtf(var + 1e-6f);
    v0 = cW[OFF_LNW + BR * 5 + 0] * (d0 * inv) + cW[OFF_LNB + BR * 5 + 0];
    v1 = cW[OFF_LNW + BR * 5 + 1] * (d1 * inv) + cW[OFF_LNB + BR * 5 + 1];
    v2 = cW[OFF_LNW + BR * 5 + 2] * (d2 * inv) + cW[OFF_LNB + BR * 5 + 2];
    v3 = cW[OFF_LNW + BR * 5 + 3] * (d3 * inv) + cW[OFF_LNB + BR * 5 + 3];
    v4 = cW[OFF_LNW + BR * 5 + 4] * (d4 * inv) + cW[OFF_LNB + BR * 5 + 4];
    S[0][sr][sc] = in ? v0 : 0.f;
    S[1][sr][sc] = in ? v1 : 0.f;
    S[2][sr][sc] = in ? v2 : 0.f;
    S[3][sr][sc] = in ? v3 : 0.f;
    S[4][sr][sc] = in ? v4 : 0.f;
}

// ---------------------------------------------------------------------------
// Per-branch body. Template BR folds weight indices into FFMA operands.
// Phase 1: 2 unconditional items + 1 predicated, straight-line for MLP.
// Phases 2/3 packed loads/FFMA2; phase 4 vertical pixel pair per thread.
// Block = 256 threads, tile 32x16.
// ---------------------------------------------------------------------------
template<int BR>
__device__ __forceinline__ void do_branch(
    int tid, int x0, int y0, int b,
    const float* __restrict__ xl, const float* __restrict__ mask,
    float (&S)[5][20][36], float4 (&CX4)[5][10][18], float4 (&TAG4)[5][8][16],
    const float2* __restrict__ sWW2, const float2* __restrict__ sWS2,
    float* pA, float* pB, float& s1A, float& s2A, float& s1B, float& s2B)
{
    __syncthreads();   // protect S/CX/TAG reuse across branches

    // ---- phase 1: 720 items = 2 full rounds + 208-item round ------------
    p1_item<BR>(tid,       x0, y0, b, xl, mask, S);
    p1_item<BR>(tid + 256, x0, y0, b, xl, mask, S);
    if (tid < 208)
        p1_item<BR>(tid + 512, x0, y0, b, xl, mask, S);
    __syncthreads();

    // ---- phase 2: Haar butterflies, 2 cells/item via LDS.128 ------------
    for (int t = tid; t < 450; t += 256) {
        int c = t / 90; int cell = t - c * 90;
        int ci = cell / 9; int cjp = cell - ci * 9;   // col pair 2cjp, 2cjp+1
        int sr = 2 * ci, sc = 4 * cjp;
        float4 r0 = *(const float4*)&S[c][sr][sc];
        float4 r1 = *(const float4*)&S[c][sr + 1][sc];
        float su1 = r0.x + r0.y, dd1 = r0.x - r0.y;
        float su2 = r1.x + r1.y, dd2 = r1.x - r1.y;
        CX4[c][ci][2 * cjp] = make_float4(0.5f * (su1 + su2), 0.5f * (su1 - su2),
                                          0.5f * (dd1 + dd2), 0.5f * (dd1 - dd2));
        float su3 = r0.z + r0.w, dd3 = r0.z - r0.w;
        float su4 = r1.z + r1.w, dd4 = r1.z - r1.w;
        CX4[c][ci][2 * cjp + 1] = make_float4(0.5f * (su3 + su4), 0.5f * (su3 - su4),
                                              0.5f * (dd3 + dd4), 0.5f * (dd3 - dd4));
    }
    __syncthreads();

    // ---- phase 3: 3x3 conv on packed subband pairs (FFMA2) -> TAG4 ------
    for (int t = tid; t < 320; t += 256) {
        int c  = t >> 6;            // 0..4
        int r  = t & 63;
        int kp = r & 1;             // subband pair (2kp, 2kp+1)
        int qj = ((r >> 1) & 3) * 4;
        int ti = r >> 3;            // 0..7
        const u64* wv2 = ((const u64*)sWW2) + ((BR * 5 + c) * 2 + kp) * 9;
        u64 a0 = 0, a1 = 0, a2 = 0, a3 = 0;
#pragma unroll
        for (int dy = 0; dy < 3; dy++) {
            u64 row[6];
#pragma unroll
            for (int dx = 0; dx < 6; dx++)
                row[dx] = ((const u64*)&CX4[c][ti + dy][qj + dx])[kp];
#pragma unroll
            for (int dx = 0; dx < 3; dx++) {
                u64 w2 = wv2[dy * 3 + dx];
                a0 = fma2(w2, row[dx],     a0);
                a1 = fma2(w2, row[dx + 1], a1);
                a2 = fma2(w2, row[dx + 2], a2);
                a3 = fma2(w2, row[dx + 3], a3);
            }
        }
        u64 ws2 = ((const u64*)sWS2)[(BR * 5 + c) * 2 + kp];
        ((u64*)&TAG4[c][ti][qj + 0])[kp] = mul2(a0, ws2);
        ((u64*)&TAG4[c][ti][qj + 1])[kp] = mul2(a1, ws2);
        ((u64*)&TAG4[c][ti][qj + 2])[kp] = mul2(a2, ws2);
        ((u64*)&TAG4[c][ti][qj + 3])[kp] = mul2(a3, ws2);
    }
    __syncthreads();

    // ---- phase 4: base conv + iDWT + pointwise for vertical pixel pair --
    {
        int tx = tid & 31, tyh = tid >> 5;   // pixels rows 2tyh, 2tyh+1
        int ci = tyh, cj = tx >> 1;
        int px = tx & 1;
        float o5A[5] = {0.f, 0.f, 0.f, 0.f, 0.f};
        float o5B[5] = {0.f, 0.f, 0.f, 0.f, 0.f};
#pragma unroll
        for (int c = 0; c < 5; c++) {
            float w4[4][3];
#pragma unroll
            for (int dy = 0; dy < 4; dy++)
#pragma unroll
                for (int dx = 0; dx < 3; dx++)
                    w4[dy][dx] = S[c][2 * tyh + 1 + dy][tx + 1 + dx];
            float sA = 0.f, sB = 0.f;
#pragma unroll
            for (int dy = 0; dy < 3; dy++)
#pragma unroll
                for (int dx = 0; dx < 3; dx++) {
                    float wgt = cW[OFF_BW + (BR * 5 + c) * 9 + dy * 3 + dx];
                    sA += wgt * w4[dy][dx];
                    sB += wgt * w4[dy + 1][dx];
                }
            sA = (sA + cW[OFF_BB + BR * 5 + c]) * cW[OFF_BS + BR * 5 + c];
            sB = (sB + cW[OFF_BB + BR * 5 + c]) * cW[OFF_BS + BR * 5 + c];
            float4 tg = TAG4[c][ci][cj];           // shared by both pixels
            float t2 = px ? -tg.z : tg.z;
            float t3A = px ? -tg.w : tg.w;
            float vA = sA + 0.5f * (tg.x + tg.y + t2 + t3A);
            float t3B = px ? tg.w : -tg.w;
            float vB = sB + 0.5f * (tg.x - tg.y + t2 + t3B);
#pragma unroll
            for (int o = 0; o < 5; o++) {
                float pwv = cW[OFF_PW + BR * 25 + o * 5 + c];
                o5A[o] += pwv * vA;
                o5B[o] += pwv * vB;
            }
        }
#pragma unroll
        for (int jj = 0; jj < 5; jj++) {
            float vA = o5A[jj], vB = o5B[jj];
            s1A += vA; s2A += vA * vA;
            s1B += vB; s2B += vB * vB;
            float vsA = cW[OFF_TLW + BR * 5 + jj] * vA;
            float vsB = cW[OFF_TLW + BR * 5 + jj] * vB;
#pragma unroll
            for (int o = 0; o < 8; o++) {
                float tw = cW[OFF_TW + o * 20 + BR * 5 + jj];
                pA[o] += tw * vsA;
                pB[o] += tw * vsB;
            }
        }
    }
}

// ---------------------------------------------------------------------------
// Kernel 2: fused branches + tail + residual.
// 32x16 tile, 256 threads, vertical pixel pair per thread, 4 blocks/SM.
// ---------------------------------------------------------------------------
__global__ __launch_bounds__(256, 4) void fused_kernel(
    const float* __restrict__ xl,        // [8,8,512,512]
    const float* __restrict__ mask,      // [8,1,512,512]
    const float* __restrict__ g_wt_w,    // [4,20,3,3]
    const float* __restrict__ g_wt_s,    // [4,20]
    float* __restrict__ out)             // [8,8,512,512]
{
    __shared__ float2 sWW2[360];         // packed (k, k+1) wavelet weights
    __shared__ float2 sWS2[40];
    __shared__ float sRS[8];             // row sums of folded tail matrix
    __shared__ float sC[8];              // folded LN-bias + tail bias
    __shared__ __align__(16) float  S[5][20][36];
    __shared__ float4 CX4[5][10][18];
    __shared__ float4 TAG4[5][8][16];

    const int tid = threadIdx.x;
    for (int t = tid; t < 360; t += 256) {
        int pairIdx = t / 9, tap = t - (t / 9) * 9;
        int chbase = (pairIdx >> 1) * 4 + (pairIdx & 1) * 2;
        sWW2[t] = make_float2(g_wt_w[chbase * 9 + tap], g_wt_w[(chbase + 1) * 9 + tap]);
    }
    for (int t = tid; t < 40; t += 256) {
        int base = (t >> 1) * 4 + (t & 1) * 2;
        sWS2[t] = make_float2(g_wt_s[base], g_wt_s[base + 1]);
    }
    if (tid < 8) {
        float rs = 0.f, C = cW[OFF_TB + tid];
#pragma unroll
        for (int j = 0; j < 20; j++) {
            float w = cW[OFF_TW + tid * 20 + j];
            rs += w * cW[OFF_TLW + j];
            C  += w * cW[OFF_TLB + j];
        }
        sRS[tid] = rs;
        sC[tid]  = C;
    }

    const int x0 = blockIdx.x * 32;
    const int y0 = blockIdx.y * 16;
    const int b  = blockIdx.z;

    float pA[8] = {0.f, 0.f, 0.f, 0.f, 0.f, 0.f, 0.f, 0.f};
    float pB[8] = {0.f, 0.f, 0.f, 0.f, 0.f, 0.f, 0.f, 0.f};
    float s1A = 0.f, s2A = 0.f, s1B = 0.f, s2B = 0.f;

    do_branch<0>(tid, x0, y0, b, xl, mask, S, CX4, TAG4, sWW2, sWS2, pA, pB, s1A, s2A, s1B, s2B);
    do_branch<1>(tid, x0, y0, b, xl, mask, S, CX4, TAG4, sWW2, sWS2, pA, pB, s1A, s2A, s1B, s2B);
    do_branch<2>(tid, x0, y0, b, xl, mask, S, CX4, TAG4, sWW2, sWS2, pA, pB, s1A, s2A, s1B, s2B);
    do_branch<3>(tid, x0, y0, b, xl, mask, S, CX4, TAG4, sWW2, sWS2, pA, pB, s1A, s2A, s1B, s2B);

    // ---- tail: folded LN(20)+matmul -> fast exact GELU, + residual ------
    const int tx = tid & 31, tyh = tid >> 5;
#pragma unroll
    for (int pp = 0; pp < 2; pp++) {
        float* p  = pp ? pB : pA;
        float s1  = pp ? s1B : s1A;
        float s2  = pp ? s2B : s2A;
        float u   = s1 * 0.05f;
        float var = fmaxf(s2 * 0.05f - u * u, 0.f);
        float inv = rsqrtf(var + 1e-6f);

        int y = y0 + 2 * tyh + pp, x = x0 + tx;
        size_t pix = (size_t)y * 512 + x;
        float xv[8];
#pragma unroll
        for (int c = 0; c < 8; c++)
            xv[c] = __ldg(xl + ((size_t)b * 8 + c) * 262144 + pix);
        float mv = __ldg(mask + (size_t)b * 262144 + pix);

#pragma unroll
        for (int o = 0; o < 8; o++) {
            float t = inv * (p[o] - u * sRS[o]) + sC[o];
            float gel = gelu_fast(t);
            float r = cW[OFF_RB + o];
#pragma unroll
            for (int c = 0; c < 8; c++) r += cW[OFF_RW + o * 9 + c] * xv[c];
            r += cW[OFF_RW + o * 9 + 8] * mv;
            out[((size_t)b * 8 + o) * 262144 + pix] = gel + r;
        }
    }
}

// ---------------------------------------------------------------------------
// kernel_launch
// Inputs: 0 xh, 1 xl, 2 mask, 3 pre_w, 4 pre_b, 5 g_ln_w, 6 g_ln_b,
//  7 g_base_w, 8 g_base_b, 9 g_base_s, 10 g_wt_w, 11 g_wt_s, 12 g_pw_w,
// 13 tail_ln_w, 14 tail_ln_b, 15 tail_w, 16 tail_b, 17 res_w, 18 res_b
// ---------------------------------------------------------------------------
extern "C" void kernel_launch(void* const* d_in, const int* in_sizes, int n_in,
                              void* d_out, int out_size)
{
    (void)in_sizes; (void)n_in; (void)out_size;
    const float* xh   = (const float*)d_in[0];
    const float* xl   = (const float*)d_in[1];
    const float* mask = (const float*)d_in[2];
    float* out = (float*)d_out;

    pack_kernel<<<(W_TOTAL + 255) / 256, 256>>>(
        (const float*)d_in[5],  (const float*)d_in[6],
        (const float*)d_in[7],  (const float*)d_in[8],
        (const float*)d_in[9],  (const float*)d_in[10],
        (const float*)d_in[11], (const float*)d_in[12],
        (const float*)d_in[13], (const float*)d_in[14],
        (const float*)d_in[15], (const float*)d_in[16],
        (const float*)d_in[17], (const float*)d_in[18],
        (const float*)d_in[3],  (const float*)d_in[4]);

    void* wpack_ptr = nullptr;
    cudaGetSymbolAddress(&wpack_ptr, g_wpack);
    cudaMemcpyToSymbolAsync(cW, wpack_ptr, W_TOTAL * sizeof(float), 0,
                            cudaMemcpyDeviceToDevice, 0);

    pre_kernel<<<2048, 256>>>(xh);

    dim3 grid(512 / 32, 512 / 16, 8);   // 16 x 32 x 8 tiles
    fused_kernel<<<grid, 256>>>(xl, mask,
                                (const float*)d_in[10], (const float*)d_in[11],
                                out);
}